// round 1
// baseline (speedup 1.0000x reference)
#include <cuda_runtime.h>
#include <math.h>
#include <stdint.h>

#define TT 8
#define FIN 128
#define HH 128
#define NMAX 50048
#define G4 (4*HH)

// ---------------- device scratch (allocation-free rule: __device__ globals) ----
static __device__ float g_feats[(size_t)TT * NMAX * HH];   // GCN outputs per t
static __device__ float g_nis[NMAX];                       // deg^{-1/2}
static __device__ float g_hlin[(size_t)NMAX * HH];         // x@W+b buffer
static __device__ float g_buf2[(size_t)NMAX * HH];         // layer1 output
static __device__ float g_agg[(size_t)NMAX * HH];          // scatter accumulator
static __device__ float g_gates[(size_t)NMAX * G4];        // LSTM gates
static __device__ float g_state[(size_t)4 * NMAX * HH];    // h1,c1,h2,c2
static __device__ float g_B1[2 * HH * G4];                 // [256,512] = [Wih1^T ; Whh1^T]
static __device__ float g_B2[2 * HH * G4];
static __device__ float g_bias1[G4];
static __device__ float g_bias2[G4];
static __device__ int   g_idx64;                           // edge_index dtype flag

// ---------------- small helpers ----------------
__device__ __forceinline__ int load_idx(const void* p, size_t off) {
    return g_idx64 ? (int)((const long long*)p)[off] : ((const int*)p)[off];
}
__device__ __forceinline__ float sigm(float x) { return 1.0f / (1.0f + expf(-x)); }

// Detect whether edge_index buffer is int64 or int32.
// If int64 (values < 2^31), every odd 32-bit word is 0. For int32 random
// indices in [0,50000), 128 consecutive odd words all being zero is impossible.
__global__ void detect_idx_kernel(const void* ei) {
    const int* p = (const int*)ei;
    int s = 0;
    for (int i = 1; i < 257; i += 2) s |= p[i];
    g_idx64 = (s == 0) ? 1 : 0;
}

// Build concatenated transposed LSTM weight matrices + fused biases.
__global__ void prep_weights_kernel(const float* __restrict__ wih1, const float* __restrict__ whh1,
                                    const float* __restrict__ bih1, const float* __restrict__ bhh1,
                                    const float* __restrict__ wih2, const float* __restrict__ whh2,
                                    const float* __restrict__ bih2, const float* __restrict__ bhh2) {
    int idx = blockIdx.x * blockDim.x + threadIdx.x;
    if (idx < 2 * HH * G4) {
        int k = idx / G4;      // 0..255
        int n = idx % G4;      // 0..511
        if (k < HH) {
            g_B1[idx] = wih1[n * HH + k];
            g_B2[idx] = wih2[n * HH + k];
        } else {
            g_B1[idx] = whh1[n * HH + (k - HH)];
            g_B2[idx] = whh2[n * HH + (k - HH)];
        }
    }
    if (idx < G4) {
        g_bias1[idx] = bih1[idx] + bhh1[idx];
        g_bias2[idx] = bih2[idx] + bhh2[idx];
    }
}

// ---------------- GCN kernels ----------------
__global__ void deg_kernel(const void* __restrict__ ei, size_t dstOff, int E, float* __restrict__ deg) {
    int i = blockIdx.x * blockDim.x + threadIdx.x;
    if (i >= E) return;
    int d = load_idx(ei, dstOff + (size_t)i);
    atomicAdd(&deg[d], 1.0f);
}

__global__ void nis_kernel(float* __restrict__ nis, int n) {
    int i = blockIdx.x * blockDim.x + threadIdx.x;
    if (i < n) nis[i] = rsqrtf(nis[i] + 1.0f);
}

// warp per edge: gather h[src] (512B contiguous), scale, vector-atomic scatter to agg[dst]
__global__ void edge_msg_kernel(const void* __restrict__ ei, size_t srcOff, size_t dstOff, int E,
                                const float* __restrict__ nis, const float* __restrict__ h,
                                float* __restrict__ agg) {
    int gw = (blockIdx.x * blockDim.x + threadIdx.x) >> 5;
    int lane = threadIdx.x & 31;
    if (gw >= E) return;
    int s = load_idx(ei, srcOff + (size_t)gw);
    int d = load_idx(ei, dstOff + (size_t)gw);
    float coeff = nis[s] * nis[d];
    float4 v = ((const float4*)(h + (size_t)s * HH))[lane];
    v.x *= coeff; v.y *= coeff; v.z *= coeff; v.w *= coeff;
    atomicAdd(((float4*)(agg + (size_t)d * HH)) + lane, v);   // red.global.v4.f32 (sm_90+)
}

__global__ void gcn_combine_kernel(const float* __restrict__ agg, const float* __restrict__ hlin,
                                   const float* __restrict__ nis, float* __restrict__ out, int n) {
    int idx = blockIdx.x * blockDim.x + threadIdx.x;
    if (idx >= n * HH) return;
    int node = idx >> 7;
    float s = nis[node];
    out[idx] = fmaxf(agg[idx] + hlin[idx] * s * s, 0.0f);
}

// ---------------- SGEMM: C[M,Nt] = [A1|A2][M,K] @ B[K,Nt] + bias ----------------
// A1, A2 row-major with lda=128 each (A2 may be null -> K=128).
#define BM 128
#define BN 128
#define BK 8
#define TM 8
#define TN 8

__global__ __launch_bounds__(256) void sgemm_kernel(
    int M, int Nt,
    const float* __restrict__ A1, const float* __restrict__ A2,
    const float* __restrict__ B, const float* __restrict__ bias,
    float* __restrict__ C) {
    __shared__ float As[BK][BM];
    __shared__ float Bs[BK][BN];
    const int tid = threadIdx.x;
    const int row0 = blockIdx.y * BM;
    const int col0 = blockIdx.x * BN;
    const int tx = tid & 15;
    const int ty = tid >> 4;
    const int aRow = tid >> 1;
    const int aCol = (tid & 1) * 4;
    const int bRow = tid >> 5;
    const int bCol = (tid & 31) * 4;
    const int K = A2 ? 256 : 128;

    float acc[TM][TN];
#pragma unroll
    for (int i = 0; i < TM; i++)
#pragma unroll
        for (int j = 0; j < TN; j++) acc[i][j] = 0.0f;

    for (int k0 = 0; k0 < K; k0 += BK) {
        const float* Ap = (k0 < 128) ? A1 : A2;
        int kk = (k0 < 128) ? k0 : (k0 - 128);
        int gr = row0 + aRow;
        float4 av = make_float4(0.f, 0.f, 0.f, 0.f);
        if (gr < M) av = *(const float4*)(Ap + (size_t)gr * 128 + kk + aCol);
        As[aCol + 0][aRow] = av.x;
        As[aCol + 1][aRow] = av.y;
        As[aCol + 2][aRow] = av.z;
        As[aCol + 3][aRow] = av.w;
        *(float4*)&Bs[bRow][bCol] = *(const float4*)(B + (size_t)(k0 + bRow) * Nt + col0 + bCol);
        __syncthreads();
#pragma unroll
        for (int k = 0; k < BK; k++) {
            float ra[TM], rb[TN];
#pragma unroll
            for (int i = 0; i < TM; i++) ra[i] = As[k][ty * TM + i];
#pragma unroll
            for (int j = 0; j < TN; j++) rb[j] = Bs[k][tx * TN + j];
#pragma unroll
            for (int i = 0; i < TM; i++)
#pragma unroll
                for (int j = 0; j < TN; j++) acc[i][j] += ra[i] * rb[j];
        }
        __syncthreads();
    }

#pragma unroll
    for (int i = 0; i < TM; i++) {
        int gr = row0 + ty * TM + i;
        if (gr < M) {
#pragma unroll
            for (int j = 0; j < TN; j += 4) {
                int gc = col0 + tx * TN + j;
                float4 v;
                v.x = acc[i][j + 0] + bias[gc + 0];
                v.y = acc[i][j + 1] + bias[gc + 1];
                v.z = acc[i][j + 2] + bias[gc + 2];
                v.w = acc[i][j + 3] + bias[gc + 3];
                *(float4*)(C + (size_t)gr * Nt + gc) = v;
            }
        }
    }
}

// ---------------- LSTM elementwise ----------------
__global__ void lstm_cell_kernel(const float* __restrict__ gates, float* __restrict__ h,
                                 float* __restrict__ c, int n) {
    int idx = blockIdx.x * blockDim.x + threadIdx.x;
    if (idx >= n * HH) return;
    int node = idx >> 7;
    int j = idx & 127;
    size_t base = (size_t)node * G4 + j;
    float ig = gates[base];
    float fg = gates[base + 128];
    float gg = gates[base + 256];
    float og = gates[base + 384];
    float cn = sigm(fg) * c[idx] + sigm(ig) * tanhf(gg);
    c[idx] = cn;
    h[idx] = sigm(og) * tanhf(cn);
}

// warp per node: out = h2 . out_w + out_b
__global__ void out_proj_kernel(const float* __restrict__ h2, const float* __restrict__ w,
                                const float* __restrict__ b, float* __restrict__ out, int n) {
    int gw = (blockIdx.x * blockDim.x + threadIdx.x) >> 5;
    int lane = threadIdx.x & 31;
    if (gw >= n) return;
    float4 hv = ((const float4*)(h2 + (size_t)gw * HH))[lane];
    float4 wv = ((const float4*)w)[lane];
    float s = hv.x * wv.x + hv.y * wv.y + hv.z * wv.z + hv.w * wv.w;
#pragma unroll
    for (int off = 16; off; off >>= 1) s += __shfl_xor_sync(0xFFFFFFFFu, s, off);
    if (lane == 0) out[gw] = s + b[0];
}

__global__ void copy_states_kernel(const float* __restrict__ st, float* __restrict__ out, size_t nh) {
    size_t i = (size_t)blockIdx.x * blockDim.x + threadIdx.x;
    size_t total = 4 * nh;
    for (; i < total; i += (size_t)gridDim.x * blockDim.x) out[i] = st[i];
}

// ---------------- host launch ----------------
static inline int cdiv(int a, int b) { return (a + b - 1) / b; }

extern "C" void kernel_launch(void* const* d_in, const int* in_sizes, int n_in,
                              void* d_out, int out_size) {
    const float* x    = (const float*)d_in[0];
    const void*  ei   = d_in[1];
    const float* gw1  = (const float*)d_in[2];
    const float* gb1  = (const float*)d_in[3];
    const float* gw2  = (const float*)d_in[4];
    const float* gb2  = (const float*)d_in[5];
    const float* wih1 = (const float*)d_in[6];
    const float* whh1 = (const float*)d_in[7];
    const float* bih1 = (const float*)d_in[8];
    const float* bhh1 = (const float*)d_in[9];
    const float* wih2 = (const float*)d_in[10];
    const float* whh2 = (const float*)d_in[11];
    const float* bih2 = (const float*)d_in[12];
    const float* bhh2 = (const float*)d_in[13];
    const float* outw = (const float*)d_in[14];
    const float* outb = (const float*)d_in[15];

    const int N = in_sizes[0] / (TT * FIN);
    const int E = in_sizes[1] / (2 * TT);
    float* out = (float*)d_out;

    float *feats, *nis, *hlin, *buf2, *agg, *gates, *state, *B1, *B2, *bias1, *bias2;
    cudaGetSymbolAddress((void**)&feats, g_feats);
    cudaGetSymbolAddress((void**)&nis,   g_nis);
    cudaGetSymbolAddress((void**)&hlin,  g_hlin);
    cudaGetSymbolAddress((void**)&buf2,  g_buf2);
    cudaGetSymbolAddress((void**)&agg,   g_agg);
    cudaGetSymbolAddress((void**)&gates, g_gates);
    cudaGetSymbolAddress((void**)&state, g_state);
    cudaGetSymbolAddress((void**)&B1,    g_B1);
    cudaGetSymbolAddress((void**)&B2,    g_B2);
    cudaGetSymbolAddress((void**)&bias1, g_bias1);
    cudaGetSymbolAddress((void**)&bias2, g_bias2);

    const size_t NH = (size_t)N * HH;

    detect_idx_kernel<<<1, 1>>>(ei);
    prep_weights_kernel<<<cdiv(2 * HH * G4, 256), 256>>>(wih1, whh1, bih1, bhh1,
                                                         wih2, whh2, bih2, bhh2);

    // -------- GCN per timestep --------
    for (int t = 0; t < TT; t++) {
        size_t srcOff = (size_t)t * 2 * E;
        size_t dstOff = srcOff + E;
        const float* xt = x + (size_t)t * N * FIN;

        cudaMemsetAsync(nis, 0, (size_t)N * sizeof(float));
        deg_kernel<<<cdiv(E, 256), 256>>>(ei, dstOff, E, nis);
        nis_kernel<<<cdiv(N, 256), 256>>>(nis, N);

        // layer 1
        sgemm_kernel<<<dim3(1, cdiv(N, BM)), 256>>>(N, HH, xt, nullptr, gw1, gb1, hlin);
        cudaMemsetAsync(agg, 0, NH * sizeof(float));
        edge_msg_kernel<<<cdiv(E * 32, 256), 256>>>(ei, srcOff, dstOff, E, nis, hlin, agg);
        gcn_combine_kernel<<<cdiv(N * HH, 256), 256>>>(agg, hlin, nis, buf2, N);

        // layer 2
        sgemm_kernel<<<dim3(1, cdiv(N, BM)), 256>>>(N, HH, buf2, nullptr, gw2, gb2, hlin);
        cudaMemsetAsync(agg, 0, NH * sizeof(float));
        edge_msg_kernel<<<cdiv(E * 32, 256), 256>>>(ei, srcOff, dstOff, E, nis, hlin, agg);
        gcn_combine_kernel<<<cdiv(N * HH, 256), 256>>>(agg, hlin, nis, feats + (size_t)t * NH, N);
    }

    // -------- LSTM over time --------
    cudaMemsetAsync(state, 0, 4 * NH * sizeof(float));
    float* h1 = state;
    float* c1 = state + NH;
    float* h2 = state + 2 * NH;
    float* c2 = state + 3 * NH;

    for (int t = 0; t < TT; t++) {
        const float* ft = feats + (size_t)t * NH;
        // layer 1 gates: ft@Wih1^T + h1@Whh1^T + bias
        sgemm_kernel<<<dim3(G4 / BN, cdiv(N, BM)), 256>>>(N, G4, ft, h1, B1, bias1, gates);
        lstm_cell_kernel<<<cdiv(N * HH, 256), 256>>>(gates, h1, c1, N);
        // layer 2 gates: h1@Wih2^T + h2@Whh2^T + bias
        sgemm_kernel<<<dim3(G4 / BN, cdiv(N, BM)), 256>>>(N, G4, h1, h2, B2, bias2, gates);
        lstm_cell_kernel<<<cdiv(N * HH, 256), 256>>>(gates, h2, c2, N);
        // output projection
        out_proj_kernel<<<cdiv(N * 32, 256), 256>>>(h2, outw, outb, out + (size_t)t * N, N);
    }

    // -------- tail: h1, c1, h2, c2 after outs --------
    copy_states_kernel<<<1024, 256>>>(state, out + (size_t)TT * N, NH);
}

// round 3
// speedup vs baseline: 1.7676x; 1.7676x over previous
#include <cuda_runtime.h>
#include <cuda_bf16.h>
#include <math.h>
#include <stdint.h>

#define TT 8
#define FIN 128
#define HH 128
#define NMAX 50048
#define G4 (4*HH)

// ---------------- device scratch (allocation-free rule: __device__ globals) ----
static __device__ __nv_bfloat16 g_xh[(size_t)TT * NMAX * HH];
static __device__ __nv_bfloat16 g_xl[(size_t)TT * NMAX * HH];
static __device__ __nv_bfloat16 g_fh[(size_t)TT * NMAX * HH];   // feats hi
static __device__ __nv_bfloat16 g_fl[(size_t)TT * NMAX * HH];   // feats lo
static __device__ __nv_bfloat16 g_b2h[(size_t)NMAX * HH];       // gcn layer1 out hi
static __device__ __nv_bfloat16 g_b2l[(size_t)NMAX * HH];
static __device__ float g_nis[NMAX];
static __device__ float g_hlin[(size_t)NMAX * HH];
static __device__ float g_agg[(size_t)NMAX * HH];
static __device__ float g_hbuf[(size_t)2 * NMAX * HH];          // fp32 h ping-pong (B bufs)
static __device__ float g_state[(size_t)4 * NMAX * HH];         // h1a,c1,h2a,c2
// h split planes, ping-pong A/B for h1 and h2
static __device__ __nv_bfloat16 g_h1h_a[(size_t)NMAX * HH];
static __device__ __nv_bfloat16 g_h1l_a[(size_t)NMAX * HH];
static __device__ __nv_bfloat16 g_h1h_b[(size_t)NMAX * HH];
static __device__ __nv_bfloat16 g_h1l_b[(size_t)NMAX * HH];
static __device__ __nv_bfloat16 g_h2h_a[(size_t)NMAX * HH];
static __device__ __nv_bfloat16 g_h2l_a[(size_t)NMAX * HH];
static __device__ __nv_bfloat16 g_h2h_b[(size_t)NMAX * HH];
static __device__ __nv_bfloat16 g_h2l_b[(size_t)NMAX * HH];
// weights: gate-interleaved LSTM B [n'=4j+g][k] hi/lo, GCN W^T [n][k] hi/lo
static __device__ __nv_bfloat16 g_B1h[512 * 256];
static __device__ __nv_bfloat16 g_B1l[512 * 256];
static __device__ __nv_bfloat16 g_B2h[512 * 256];
static __device__ __nv_bfloat16 g_B2l[512 * 256];
static __device__ __nv_bfloat16 g_GW1h[128 * 128];
static __device__ __nv_bfloat16 g_GW1l[128 * 128];
static __device__ __nv_bfloat16 g_GW2h[128 * 128];
static __device__ __nv_bfloat16 g_GW2l[128 * 128];
static __device__ float g_bias1[G4];
static __device__ float g_bias2[G4];
static __device__ int   g_idx64;

// ---------------- helpers ----------------
__device__ __forceinline__ int load_idx(const void* p, size_t off) {
    return g_idx64 ? (int)((const long long*)p)[off] : ((const int*)p)[off];
}
__device__ __forceinline__ float sigm(float x) { return 1.0f / (1.0f + expf(-x)); }

__device__ __forceinline__ void split_bf16(float v, __nv_bfloat16& h, __nv_bfloat16& l) {
    h = __float2bfloat16(v);
    l = __float2bfloat16(v - __bfloat162float(h));
}

__device__ __forceinline__ void cpasync16(uint32_t dst, const void* src, int sz) {
    asm volatile("cp.async.cg.shared.global [%0], [%1], 16, %2;\n" :: "r"(dst), "l"(src), "r"(sz));
}
__device__ __forceinline__ void cp_commit() { asm volatile("cp.async.commit_group;\n"); }
__device__ __forceinline__ void cp_wait1() { asm volatile("cp.async.wait_group 1;\n"); }

__device__ __forceinline__ uint32_t swz(uint32_t o) { return o ^ ((o >> 3) & 0x10); }

__device__ __forceinline__ void ldsm4(uint32_t* r, uint32_t addr) {
    asm volatile("ldmatrix.sync.aligned.m8n8.x4.shared.b16 {%0,%1,%2,%3}, [%4];"
                 : "=r"(r[0]), "=r"(r[1]), "=r"(r[2]), "=r"(r[3]) : "r"(addr));
}

__device__ __forceinline__ void mma_bf16(float* d, const uint32_t* a, const uint32_t* b) {
    asm volatile(
        "mma.sync.aligned.m16n8k16.row.col.f32.bf16.bf16.f32 "
        "{%0,%1,%2,%3}, {%4,%5,%6,%7}, {%8,%9}, {%0,%1,%2,%3};\n"
        : "+f"(d[0]), "+f"(d[1]), "+f"(d[2]), "+f"(d[3])
        : "r"(a[0]), "r"(a[1]), "r"(a[2]), "r"(a[3]), "r"(b[0]), "r"(b[1]));
}

// Detect whether edge_index buffer is int64 or int32.
__global__ void detect_idx_kernel(const void* ei) {
    const int* p = (const int*)ei;
    int s = 0;
    for (int i = 1; i < 257; i += 2) s |= p[i];
    g_idx64 = (s == 0) ? 1 : 0;
}

// split x into bf16 hi/lo planes
__global__ void split_x_kernel(const float* __restrict__ x, size_t total) {
    for (size_t i = (size_t)blockIdx.x * blockDim.x + threadIdx.x; i < total;
         i += (size_t)gridDim.x * blockDim.x) {
        split_bf16(x[i], g_xh[i], g_xl[i]);
    }
}

// Build split weight planes + fused biases.
__global__ void prep_weights_kernel(const float* __restrict__ gw1, const float* __restrict__ gw2,
                                    const float* __restrict__ wih1, const float* __restrict__ whh1,
                                    const float* __restrict__ bih1, const float* __restrict__ bhh1,
                                    const float* __restrict__ wih2, const float* __restrict__ whh2,
                                    const float* __restrict__ bih2, const float* __restrict__ bhh2) {
    int idx = blockIdx.x * blockDim.x + threadIdx.x;
    if (idx < 512 * 256) {
        int n = idx >> 8;       // gate-interleaved col
        int k = idx & 255;
        int j = n >> 2, g = n & 3;
        int orow = g * 128 + j;
        float v1, v2;
        if (k < 128) { v1 = wih1[orow * 128 + k];         v2 = wih2[orow * 128 + k]; }
        else         { v1 = whh1[orow * 128 + (k - 128)]; v2 = whh2[orow * 128 + (k - 128)]; }
        split_bf16(v1, g_B1h[idx], g_B1l[idx]);
        split_bf16(v2, g_B2h[idx], g_B2l[idx]);
    }
    if (idx < 128 * 128) {
        int n = idx >> 7, k = idx & 127;
        split_bf16(gw1[k * 128 + n], g_GW1h[idx], g_GW1l[idx]);
        split_bf16(gw2[k * 128 + n], g_GW2h[idx], g_GW2l[idx]);
    }
    if (idx < 512) {
        int j = idx >> 2, g = idx & 3;
        int orow = g * 128 + j;
        g_bias1[idx] = bih1[orow] + bhh1[orow];
        g_bias2[idx] = bih2[orow] + bhh2[orow];
    }
}

// ---------------- GCN kernels ----------------
__global__ void deg_kernel(const void* __restrict__ ei, size_t dstOff, int E, float* __restrict__ deg) {
    int i = blockIdx.x * blockDim.x + threadIdx.x;
    if (i >= E) return;
    int d = load_idx(ei, dstOff + (size_t)i);
    atomicAdd(&deg[d], 1.0f);
}

__global__ void nis_kernel(float* __restrict__ nis, int n) {
    int i = blockIdx.x * blockDim.x + threadIdx.x;
    if (i < n) nis[i] = rsqrtf(nis[i] + 1.0f);
}

__global__ void edge_msg_kernel(const void* __restrict__ ei, size_t srcOff, size_t dstOff, int E,
                                const float* __restrict__ nis, const float* __restrict__ h,
                                float* __restrict__ agg) {
    int gw = (blockIdx.x * blockDim.x + threadIdx.x) >> 5;
    int lane = threadIdx.x & 31;
    if (gw >= E) return;
    int s = load_idx(ei, srcOff + (size_t)gw);
    int d = load_idx(ei, dstOff + (size_t)gw);
    float coeff = nis[s] * nis[d];
    float4 v = ((const float4*)(h + (size_t)s * HH))[lane];
    v.x *= coeff; v.y *= coeff; v.z *= coeff; v.w *= coeff;
    atomicAdd(((float4*)(agg + (size_t)d * HH)) + lane, v);
}

// combine + relu, write split bf16 planes
__global__ void gcn_combine_kernel(const float* __restrict__ agg, const float* __restrict__ hlin,
                                   const float* __restrict__ nis,
                                   __nv_bfloat16* __restrict__ oh, __nv_bfloat16* __restrict__ ol,
                                   int n) {
    int idx = blockIdx.x * blockDim.x + threadIdx.x;
    if (idx >= n * HH) return;
    int node = idx >> 7;
    float s = nis[node];
    float v = fmaxf(agg[idx] + hlin[idx] * s * s, 0.0f);
    split_bf16(v, oh[idx], ol[idx]);
}

// ---------------- emulated-fp32 GEMM via bf16x2 (3-term) tensor mma ----------
// C[M,Nt] = [A1|A2][M,K] @ Bt^T + bias; operands as hi/lo bf16 planes,
// A row-major lda=128 per plane (A2 null -> K=128); Bt K-major [Nt][K].
// LSTM=true: gate-interleaved epilogue computes the cell: updates cstate,
// writes fp32 h and split h planes.
#define BM 128
#define BN 128
#define BKK 16

template<bool LSTM>
__global__ __launch_bounds__(256) void mma_gemm_kernel(
    int M, int Nt, int K,
    const __nv_bfloat16* __restrict__ A1h, const __nv_bfloat16* __restrict__ A1l,
    const __nv_bfloat16* __restrict__ A2h, const __nv_bfloat16* __restrict__ A2l,
    const __nv_bfloat16* __restrict__ Bth, const __nv_bfloat16* __restrict__ Btl,
    const float* __restrict__ bias,
    float* __restrict__ Cout, float* __restrict__ cstate,
    float* __restrict__ hout, __nv_bfloat16* __restrict__ houth, __nv_bfloat16* __restrict__ houtl) {

    // stage layout (bytes): Ah 0..4095, Al 4096.., Bh 8192.., Bl 12288..; x2 stages
    __shared__ __align__(16) char smemc[34048];  // >= max(2*16384, 64*132*4)
    const uint32_t smemBase = (uint32_t)__cvta_generic_to_shared(smemc);

    const int tid = threadIdx.x;
    const int lane = tid & 31;
    const int wid = tid >> 5;
    const int wm = wid >> 2;          // 0..1
    const int wn = wid & 3;           // 0..3
    const int row0 = blockIdx.y * BM;
    const int col0 = blockIdx.x * BN;

    float acc[4][4][4];
#pragma unroll
    for (int i = 0; i < 4; i++)
#pragma unroll
        for (int j = 0; j < 4; j++)
#pragma unroll
            for (int v = 0; v < 4; v++) acc[i][j][v] = 0.0f;

    const int KT = K / BKK;

    // per-thread load slot: one 16B chunk per plane-tile
    const int lrow = tid >> 1;        // 0..127
    const int lh = tid & 1;           // k-half
    const uint32_t dOff = swz((uint32_t)(lrow * 32 + lh * 16));

    auto load_tile = [&](int kt, int buf) {
        const int k0 = kt * BKK;
        const __nv_bfloat16 *Aph, *Apl;
        int kk;
        if (k0 < 128) { Aph = A1h; Apl = A1l; kk = k0; }
        else          { Aph = A2h; Apl = A2l; kk = k0 - 128; }
        const uint32_t base = smemBase + buf * 16384;
        const int gr = row0 + lrow;
        const int pa = (gr < M) ? 16 : 0;
        const size_t aoff = (size_t)gr * 128 + kk + lh * 8;
        cpasync16(base + dOff,         Aph + aoff, pa);
        cpasync16(base + 4096 + dOff,  Apl + aoff, pa);
        const size_t boff = (size_t)(col0 + lrow) * K + k0 + lh * 8;
        cpasync16(base + 8192 + dOff,  Bth + boff, 16);
        cpasync16(base + 12288 + dOff, Btl + boff, 16);
    };

    // fragment address components
    const int a_r = lane & 15;
    const int a_h = lane >> 4;
    const int b_n = (lane & 7) + ((lane >> 4) << 3);
    const int b_h = (lane >> 3) & 1;

    load_tile(0, 0);
    cp_commit();

    for (int kt = 0; kt < KT; kt++) {
        if (kt + 1 < KT) load_tile(kt + 1, (kt + 1) & 1);
        cp_commit();
        cp_wait1();
        __syncthreads();
        const uint32_t base = smemBase + (kt & 1) * 16384;

        uint32_t ah[4][4], al[4][4], bh[4][2], bl[4][2];
#pragma unroll
        for (int mf = 0; mf < 4; mf++) {
            uint32_t ao = swz((uint32_t)((wm * 64 + mf * 16 + a_r) * 32 + a_h * 16));
            ldsm4(ah[mf], base + ao);
            ldsm4(al[mf], base + 4096 + ao);
        }
#pragma unroll
        for (int nf2 = 0; nf2 < 2; nf2++) {
            uint32_t bo = swz((uint32_t)((wn * 32 + nf2 * 16 + b_n) * 32 + b_h * 16));
            uint32_t t4[4];
            ldsm4(t4, base + 8192 + bo);
            bh[2 * nf2][0] = t4[0]; bh[2 * nf2][1] = t4[1];
            bh[2 * nf2 + 1][0] = t4[2]; bh[2 * nf2 + 1][1] = t4[3];
            ldsm4(t4, base + 12288 + bo);
            bl[2 * nf2][0] = t4[0]; bl[2 * nf2][1] = t4[1];
            bl[2 * nf2 + 1][0] = t4[2]; bl[2 * nf2 + 1][1] = t4[3];
        }
#pragma unroll
        for (int mf = 0; mf < 4; mf++)
#pragma unroll
            for (int nf = 0; nf < 4; nf++) {
                mma_bf16(acc[mf][nf], ah[mf], bh[nf]);
                mma_bf16(acc[mf][nf], ah[mf], bl[nf]);
                mma_bf16(acc[mf][nf], al[mf], bh[nf]);
            }
        __syncthreads();
    }

    if (!LSTM) {
#pragma unroll
        for (int mf = 0; mf < 4; mf++) {
            int gr = row0 + wm * 64 + mf * 16 + (lane >> 2);
#pragma unroll
            for (int nf = 0; nf < 4; nf++) {
                int gc = col0 + wn * 32 + nf * 8 + 2 * (lane & 3);
                float b0 = bias[gc], b1 = bias[gc + 1];
                if (gr < M) {
                    float2 v = make_float2(acc[mf][nf][0] + b0, acc[mf][nf][1] + b1);
                    *(float2*)(Cout + (size_t)gr * Nt + gc) = v;
                }
                if (gr + 8 < M) {
                    float2 v = make_float2(acc[mf][nf][2] + b0, acc[mf][nf][3] + b1);
                    *(float2*)(Cout + (size_t)(gr + 8) * Nt + gc) = v;
                }
            }
        }
    } else {
        // gate quads interleaved: col 4j+{i,f,g,o}; stage 64-row chunks in smem
        float (*sC)[132] = (float (*)[132])smemc;
        const int j0 = col0 >> 2;
        for (int ch = 0; ch < 2; ch++) {
            __syncthreads();
            if (wm == ch) {
#pragma unroll
                for (int mf = 0; mf < 4; mf++) {
                    int rl = mf * 16 + (lane >> 2);
#pragma unroll
                    for (int nf = 0; nf < 4; nf++) {
                        int cl = wn * 32 + nf * 8 + 2 * (lane & 3);
                        float b0 = bias[col0 + cl], b1 = bias[col0 + cl + 1];
                        sC[rl][cl] = acc[mf][nf][0] + b0;
                        sC[rl][cl + 1] = acc[mf][nf][1] + b1;
                        sC[rl + 8][cl] = acc[mf][nf][2] + b0;
                        sC[rl + 8][cl + 1] = acc[mf][nf][3] + b1;
                    }
                }
            }
            __syncthreads();
            for (int q = tid; q < 64 * 32; q += 256) {
                int rl = q >> 5, jl = q & 31;
                int node = row0 + ch * 64 + rl;
                if (node < M) {
                    float4 g4 = *(float4*)&sC[rl][4 * jl];
                    size_t ci = (size_t)node * HH + j0 + jl;
                    float cn = sigm(g4.y) * cstate[ci] + sigm(g4.x) * tanhf(g4.z);
                    cstate[ci] = cn;
                    float hv = sigm(g4.w) * tanhf(cn);
                    hout[ci] = hv;
                    split_bf16(hv, houth[ci], houtl[ci]);
                }
            }
        }
    }
}

// warp per node: out = h2 . out_w + out_b
__global__ void out_proj_kernel(const float* __restrict__ h2, const float* __restrict__ w,
                                const float* __restrict__ b, float* __restrict__ out, int n) {
    int gw = (blockIdx.x * blockDim.x + threadIdx.x) >> 5;
    int lane = threadIdx.x & 31;
    if (gw >= n) return;
    float4 hv = ((const float4*)(h2 + (size_t)gw * HH))[lane];
    float4 wv = ((const float4*)w)[lane];
    float s = hv.x * wv.x + hv.y * wv.y + hv.z * wv.z + hv.w * wv.w;
#pragma unroll
    for (int off = 16; off; off >>= 1) s += __shfl_xor_sync(0xFFFFFFFFu, s, off);
    if (lane == 0) out[gw] = s + b[0];
}

__global__ void copy_states_kernel(const float* __restrict__ st, float* __restrict__ out, size_t nh) {
    size_t i = (size_t)blockIdx.x * blockDim.x + threadIdx.x;
    size_t total = 4 * nh;
    for (; i < total; i += (size_t)gridDim.x * blockDim.x) out[i] = st[i];
}

// ---------------- host launch ----------------
static inline int cdiv(int a, int b) { return (a + b - 1) / b; }

#define SYM(var, sym) cudaGetSymbolAddress((void**)&var, sym)

extern "C" void kernel_launch(void* const* d_in, const int* in_sizes, int n_in,
                              void* d_out, int out_size) {
    const float* x    = (const float*)d_in[0];
    const void*  ei   = d_in[1];
    const float* gw1  = (const float*)d_in[2];
    const float* gb1  = (const float*)d_in[3];
    const float* gw2  = (const float*)d_in[4];
    const float* gb2  = (const float*)d_in[5];
    const float* wih1 = (const float*)d_in[6];
    const float* whh1 = (const float*)d_in[7];
    const float* bih1 = (const float*)d_in[8];
    const float* bhh1 = (const float*)d_in[9];
    const float* wih2 = (const float*)d_in[10];
    const float* whh2 = (const float*)d_in[11];
    const float* bih2 = (const float*)d_in[12];
    const float* bhh2 = (const float*)d_in[13];
    const float* outw = (const float*)d_in[14];
    const float* outb = (const float*)d_in[15];

    const int N = in_sizes[0] / (TT * FIN);
    const int E = in_sizes[1] / (2 * TT);
    float* out = (float*)d_out;

    __nv_bfloat16 *xh, *xl, *fh, *fl, *b2h, *b2l;
    __nv_bfloat16 *h1h_a, *h1l_a, *h1h_b, *h1l_b, *h2h_a, *h2l_a, *h2h_b, *h2l_b;
    __nv_bfloat16 *B1h, *B1l, *B2h, *B2l, *GW1h, *GW1l, *GW2h, *GW2l;
    float *nis, *hlin, *agg, *hbuf, *state, *bias1, *bias2;
    SYM(xh, g_xh); SYM(xl, g_xl); SYM(fh, g_fh); SYM(fl, g_fl);
    SYM(b2h, g_b2h); SYM(b2l, g_b2l);
    SYM(h1h_a, g_h1h_a); SYM(h1l_a, g_h1l_a); SYM(h1h_b, g_h1h_b); SYM(h1l_b, g_h1l_b);
    SYM(h2h_a, g_h2h_a); SYM(h2l_a, g_h2l_a); SYM(h2h_b, g_h2h_b); SYM(h2l_b, g_h2l_b);
    SYM(B1h, g_B1h); SYM(B1l, g_B1l); SYM(B2h, g_B2h); SYM(B2l, g_B2l);
    SYM(GW1h, g_GW1h); SYM(GW1l, g_GW1l); SYM(GW2h, g_GW2h); SYM(GW2l, g_GW2l);
    SYM(nis, g_nis); SYM(hlin, g_hlin); SYM(agg, g_agg);
    SYM(hbuf, g_hbuf); SYM(state, g_state); SYM(bias1, g_bias1); SYM(bias2, g_bias2);

    const size_t NH = (size_t)N * HH;
    const int mb = cdiv(N, BM);

    detect_idx_kernel<<<1, 1>>>(ei);
    prep_weights_kernel<<<cdiv(512 * 256, 256), 256>>>(gw1, gw2, wih1, whh1, bih1, bhh1,
                                                       wih2, whh2, bih2, bhh2);
    split_x_kernel<<<2048, 256>>>(x, (size_t)TT * N * FIN);

    // -------- GCN per timestep --------
    for (int t = 0; t < TT; t++) {
        size_t srcOff = (size_t)t * 2 * E;
        size_t dstOff = srcOff + E;
        const size_t xoff = (size_t)t * N * FIN;

        cudaMemsetAsync(nis, 0, (size_t)N * sizeof(float));
        deg_kernel<<<cdiv(E, 256), 256>>>(ei, dstOff, E, nis);
        nis_kernel<<<cdiv(N, 256), 256>>>(nis, N);

        // layer 1: hlin = xt @ W1 + b1
        mma_gemm_kernel<false><<<dim3(1, mb), 256>>>(
            N, HH, 128, xh + xoff, xl + xoff, nullptr, nullptr, GW1h, GW1l, gb1,
            hlin, nullptr, nullptr, nullptr, nullptr);
        cudaMemsetAsync(agg, 0, NH * sizeof(float));
        edge_msg_kernel<<<cdiv(E * 32, 256), 256>>>(ei, srcOff, dstOff, E, nis, hlin, agg);
        gcn_combine_kernel<<<cdiv(N * HH, 256), 256>>>(agg, hlin, nis, b2h, b2l, N);

        // layer 2
        mma_gemm_kernel<false><<<dim3(1, mb), 256>>>(
            N, HH, 128, b2h, b2l, nullptr, nullptr, GW2h, GW2l, gb2,
            hlin, nullptr, nullptr, nullptr, nullptr);
        cudaMemsetAsync(agg, 0, NH * sizeof(float));
        edge_msg_kernel<<<cdiv(E * 32, 256), 256>>>(ei, srcOff, dstOff, E, nis, hlin, agg);
        gcn_combine_kernel<<<cdiv(N * HH, 256), 256>>>(agg, hlin, nis,
                                                       fh + (size_t)t * NH, fl + (size_t)t * NH, N);
    }

    // -------- LSTM over time (fused gates+cell GEMM, ping-pong h) --------
    cudaMemsetAsync(state, 0, 4 * NH * sizeof(float));
    cudaMemsetAsync(h1h_a, 0, NH * sizeof(__nv_bfloat16));
    cudaMemsetAsync(h1l_a, 0, NH * sizeof(__nv_bfloat16));
    cudaMemsetAsync(h2h_a, 0, NH * sizeof(__nv_bfloat16));
    cudaMemsetAsync(h2l_a, 0, NH * sizeof(__nv_bfloat16));

    float* h1a = state;
    float* c1  = state + NH;
    float* h2a = state + 2 * NH;
    float* c2  = state + 3 * NH;
    float* h1b = hbuf;
    float* h2b = hbuf + NH;

    for (int t = 0; t < TT; t++) {
        const int odd = t & 1;
        const __nv_bfloat16* h1ih = odd ? h1h_b : h1h_a;
        const __nv_bfloat16* h1il = odd ? h1l_b : h1l_a;
        __nv_bfloat16* h1oh = odd ? h1h_a : h1h_b;
        __nv_bfloat16* h1ol = odd ? h1l_a : h1l_b;
        const __nv_bfloat16* h2ih = odd ? h2h_b : h2h_a;
        const __nv_bfloat16* h2il = odd ? h2l_b : h2l_a;
        __nv_bfloat16* h2oh = odd ? h2h_a : h2h_b;
        __nv_bfloat16* h2ol = odd ? h2l_a : h2l_b;
        float* h1_out = odd ? h1a : h1b;
        float* h2_out = odd ? h2a : h2b;

        mma_gemm_kernel<true><<<dim3(4, mb), 256>>>(
            N, G4, 256, fh + (size_t)t * NH, fl + (size_t)t * NH, h1ih, h1il,
            B1h, B1l, bias1, nullptr, c1, h1_out, h1oh, h1ol);
        mma_gemm_kernel<true><<<dim3(4, mb), 256>>>(
            N, G4, 256, h1oh, h1ol, h2ih, h2il,
            B2h, B2l, bias2, nullptr, c2, h2_out, h2oh, h2ol);
        out_proj_kernel<<<cdiv(N * 32, 256), 256>>>(h2_out, outw, outb, out + (size_t)t * N, N);
    }

    // -------- tail: h1, c1, h2, c2 (t=7 odd -> finals in buf A = state) ------
    copy_states_kernel<<<1024, 256>>>(state, out + (size_t)TT * N, NH);
}